// round 4
// baseline (speedup 1.0000x reference)
#include <cuda_runtime.h>
#include <cstdint>

#define Tlen 1024
#define NCTA 128
#define NTHR 512

typedef unsigned long long ull;

// ---- static shared layout ----
// HC : [2][4][196]  h1(0..127) ++ h2(128..191) per batch, double buffered
// A1 : [512]        L1 gate preacts, layout [g*128 + dl*4 + b]
// A2 : [256]        L2 gate preacts, layout [g*64  + dl*4 + b]
// XS : [4][1024]    staged x
struct Smem {
    float hc[2][4][196];
    float a1[512];
    float a2[256];
    float xs[4][1024];
};

__device__ __forceinline__ float sigm(float v) { return 1.0f / (1.0f + __expf(-v)); }

__device__ __forceinline__ uint32_t s2u(const void* p) {
    uint32_t a;
    asm("{ .reg .u64 t; cvta.to.shared.u64 t, %1; cvt.u32.u64 %0, t; }" : "=r"(a) : "l"(p));
    return a;
}
__device__ __forceinline__ void stc(uint32_t saddr, int rank, float v) {
    uint32_t r;
    asm volatile("mapa.shared::cluster.u32 %0, %1, %2;" : "=r"(r) : "r"(saddr), "r"(rank));
    asm volatile("st.shared::cluster.f32 [%0], %1;" :: "r"(r), "f"(v) : "memory");
}
__device__ __forceinline__ void csync() {
    asm volatile("barrier.cluster.arrive.aligned;" ::: "memory");
    asm volatile("barrier.cluster.wait.aligned;" ::: "memory");
}
__device__ __forceinline__ void ffma2(ull& acc, ull a, ull b) {
    asm("fma.rn.f32x2 %0, %1, %2, %0;" : "+l"(acc) : "l"(a), "l"(b));
}
__device__ __forceinline__ float2 u2f2(ull u) {
    float2 f;
    asm("mov.b64 {%0, %1}, %2;" : "=f"(f.x), "=f"(f.y) : "l"(u));
    return f;
}
__device__ __forceinline__ ull pk(float lo, float hi) {
    ull r;
    asm("mov.b64 %0, {%1, %2};" : "=l"(r) : "f"(lo), "f"(hi));
    return r;
}

__global__ void __launch_bounds__(NTHR, 1) __cluster_dims__(4, 1, 1)
lstm_cluster_kernel(
    const float* __restrict__ x,      // [128][1024]
    const float* __restrict__ w_ih1,  // [512][1]
    const float* __restrict__ w_hh1,  // [512][128]
    const float* __restrict__ b_ih1,
    const float* __restrict__ b_hh1,
    const float* __restrict__ w_ih2,  // [256][128]
    const float* __restrict__ w_hh2,  // [256][64]
    const float* __restrict__ b_ih2,
    const float* __restrict__ b_hh2,
    float* __restrict__ out)          // [128][64]
{
    __shared__ Smem sm;

    const int tid = threadIdx.x;
    const int q   = blockIdx.x & 3;   // cluster rank (dim slice)
    const int cid = blockIdx.x >> 2;  // batch group: batches 4*cid..4*cid+3

    // ---------------- thread roles ----------------
    // L1 compute: row (g1, dl1) of this CTA's 32-dim slice, k-quarter ks1
    const int ks1 = tid & 3;
    const int dl1 = (tid >> 2) & 31;
    const int g1  = tid >> 7;
    // L2 compute: row (g2, dl2) of this CTA's 16-dim slice, k-eighth ks2
    const int ks2 = tid & 7;
    const int dl2 = (tid >> 3) & 15;
    const int g2  = tid >> 7;

    // ---------------- one-time: weights -> registers ----------------
    const int row1w = g1 * 128 + 32 * q + dl1;
    ulonglong2 w1u[8];
    {
        const float4* src = reinterpret_cast<const float4*>(w_hh1 + row1w * 128 + 32 * ks1);
#pragma unroll
        for (int j = 0; j < 8; j++) {
            float4 f = src[j];
            w1u[j].x = pk(f.x, f.y);
            w1u[j].y = pk(f.z, f.w);
        }
    }
    const int row2w = g2 * 64 + 16 * q + dl2;
    ulonglong2 w2u[6];
    {
#pragma unroll
        for (int jj = 0; jj < 6; jj++) {
            float f[4];
#pragma unroll
            for (int e = 0; e < 4; e++) {
                int k = 24 * ks2 + 4 * jj + e;
                f[e] = (k < 128) ? w_ih2[row2w * 128 + k] : w_hh2[row2w * 64 + (k - 128)];
            }
            w2u[jj].x = pk(f[0], f[1]);
            w2u[jj].y = pk(f[2], f[3]);
        }
    }

    // combiner constants
    float wihc[4], b1c[4];             // tid < 128 : L1 combiner for (b=tid&3, d=tid>>2)
    if (tid < 128) {
        int d = tid >> 2;
#pragma unroll
        for (int g = 0; g < 4; g++) {
            int row = g * 128 + 32 * q + d;
            wihc[g] = w_ih1[row];
            b1c[g]  = b_ih1[row] + b_hh1[row];
        }
    }
    float b2c[4];                      // tid < 64 : L2 combiner for (b=tid&3, d=tid>>2)
    if (tid < 64) {
        int d2 = 16 * q + (tid >> 2);
#pragma unroll
        for (int g = 0; g < 4; g++) b2c[g] = b_ih2[g * 64 + d2] + b_hh2[g * 64 + d2];
    }

    // ---------------- init smem: x staging + zero hc ----------------
    for (int idx = tid; idx < 4 * 1024; idx += NTHR) {
        int b = idx >> 10, t = idx & 1023;
        sm.xs[b][t] = x[(4 * cid + b) * 1024 + t];
    }
    for (int idx = tid; idx < 2 * 4 * 196; idx += NTHR)
        (&sm.hc[0][0][0])[idx] = 0.0f;

    csync();  // all cluster CTAs' smem ready

    float c1 = 0.0f, c2 = 0.0f;

    for (int i = 0; i <= Tlen; i++) {
        const int pc = i & 1, pp = pc ^ 1;

        // ---- L1 partials: all 4 batches, k-quarter, weights in regs ----
        if (i < Tlen) {
            float s[4];
#pragma unroll
            for (int b = 0; b < 4; b++) {
                const ulonglong2* hp = reinterpret_cast<const ulonglong2*>(
                    &sm.hc[pp][b][32 * ks1]);
                ull a0 = 0ull, a1 = 0ull;
#pragma unroll
                for (int kk = 0; kk < 8; kk++) {
                    ulonglong2 h = hp[kk];
                    ffma2(a0, h.x, w1u[kk].x);
                    ffma2(a1, h.y, w1u[kk].y);
                }
                float2 f0 = u2f2(a0), f1 = u2f2(a1);
                float v = (f0.x + f0.y) + (f1.x + f1.y);
                v += __shfl_xor_sync(0xffffffffu, v, 1);
                v += __shfl_xor_sync(0xffffffffu, v, 2);
                s[b] = v;
            }
            float v = (ks1 == 0) ? s[0] : (ks1 == 1) ? s[1] : (ks1 == 2) ? s[2] : s[3];
            sm.a1[g1 * 128 + dl1 * 4 + ks1] = v;
        }

        // ---- L2 partials: all 4 batches, k-eighth over [h1 ++ h2] ----
        if (i >= 1) {
            float s[4];
#pragma unroll
            for (int b = 0; b < 4; b++) {
                const ulonglong2* hp = reinterpret_cast<const ulonglong2*>(
                    &sm.hc[pp][b][24 * ks2]);
                ull a0 = 0ull, a1 = 0ull;
#pragma unroll
                for (int kk = 0; kk < 6; kk++) {
                    ulonglong2 h = hp[kk];
                    ffma2(a0, h.x, w2u[kk].x);
                    ffma2(a1, h.y, w2u[kk].y);
                }
                float2 f0 = u2f2(a0), f1 = u2f2(a1);
                float v = (f0.x + f0.y) + (f1.x + f1.y);
                v += __shfl_xor_sync(0xffffffffu, v, 1);
                v += __shfl_xor_sync(0xffffffffu, v, 2);
                v += __shfl_xor_sync(0xffffffffu, v, 4);
                s[b] = v;
            }
            if (ks2 < 4) {
                float v = (ks2 == 0) ? s[0] : (ks2 == 1) ? s[1] : (ks2 == 2) ? s[2] : s[3];
                sm.a2[g2 * 64 + dl2 * 4 + ks2] = v;
            }
        }

        __syncthreads();

        // ---- L1 combine + scatter h1 to all cluster CTAs ----
        if (i < Tlen && tid < 128) {
            int b = tid & 3, d = tid >> 2;
            float xv = sm.xs[b][i];
            float ai = fmaf(xv, wihc[0], sm.a1[tid]       + b1c[0]);
            float af = fmaf(xv, wihc[1], sm.a1[128 + tid] + b1c[1]);
            float ag = fmaf(xv, wihc[2], sm.a1[256 + tid] + b1c[2]);
            float ao = fmaf(xv, wihc[3], sm.a1[384 + tid] + b1c[3]);
            c1 = sigm(af) * c1 + sigm(ai) * tanhf(ag);
            float h = sigm(ao) * tanhf(c1);
            uint32_t dst = s2u(&sm.hc[pc][b][32 * q + d]);
            stc(dst, 0, h); stc(dst, 1, h); stc(dst, 2, h); stc(dst, 3, h);
        }

        // ---- L2 combine (one step behind) + scatter h2 / final output ----
        if (i >= 1 && tid < 64) {
            int b = tid & 3, d = tid >> 2;
            float ai = sm.a2[tid]       + b2c[0];
            float af = sm.a2[64 + tid]  + b2c[1];
            float ag = sm.a2[128 + tid] + b2c[2];
            float ao = sm.a2[192 + tid] + b2c[3];
            c2 = sigm(af) * c2 + sigm(ai) * tanhf(ag);
            float h = sigm(ao) * tanhf(c2);
            if (i == Tlen) {
                out[(4 * cid + b) * 64 + 16 * q + d] = h;
            } else {
                uint32_t dst = s2u(&sm.hc[pc][b][128 + 16 * q + d]);
                stc(dst, 0, h); stc(dst, 1, h); stc(dst, 2, h); stc(dst, 3, h);
            }
        }

        if (i < Tlen) csync();  // release our h writes / acquire peers'
    }
}

extern "C" void kernel_launch(void* const* d_in, const int* in_sizes, int n_in,
                              void* d_out, int out_size) {
    const float* x     = (const float*)d_in[0];
    const float* w_ih1 = (const float*)d_in[1];
    const float* w_hh1 = (const float*)d_in[2];
    const float* b_ih1 = (const float*)d_in[3];
    const float* b_hh1 = (const float*)d_in[4];
    const float* w_ih2 = (const float*)d_in[5];
    const float* w_hh2 = (const float*)d_in[6];
    const float* b_ih2 = (const float*)d_in[7];
    const float* b_hh2 = (const float*)d_in[8];
    float* out = (float*)d_out;

    lstm_cluster_kernel<<<NCTA, NTHR>>>(
        x, w_ih1, w_hh1, b_ih1, b_hh1, w_ih2, w_hh2, b_ih2, b_hh2, out);
    (void)in_sizes; (void)n_in; (void)out_size;
}

// round 5
// speedup vs baseline: 2.2299x; 2.2299x over previous
#include <cuda_runtime.h>
#include <cstdint>

#define Tlen 1024
#define NCTA 128
#define NTHR 512

typedef unsigned long long ull;

// ---- static shared layout ----
// HC : [2][4][196]  h1(0..127) ++ h2(128..191) per batch, double buffered
// A1 : [512]        L1 gate preacts, layout [g*128 + dl*4 + b]
// A2 : [256]        L2 gate preacts, layout [g*64  + dl*4 + b]
// XS : [4][1024]    staged x
struct Smem {
    float hc[2][4][196];
    float a1[512];
    float a2[256];
    float xs[4][1024];
};

__device__ __forceinline__ float sigm(float v) { return 1.0f / (1.0f + __expf(-v)); }

__device__ __forceinline__ uint32_t s2u(const void* p) {
    uint32_t a;
    asm("{ .reg .u64 t; cvta.to.shared.u64 t, %1; cvt.u32.u64 %0, t; }" : "=r"(a) : "l"(p));
    return a;
}
__device__ __forceinline__ void stc(uint32_t saddr, int rank, float v) {
    uint32_t r;
    asm volatile("mapa.shared::cluster.u32 %0, %1, %2;" : "=r"(r) : "r"(saddr), "r"(rank));
    asm volatile("st.shared::cluster.f32 [%0], %1;" :: "r"(r), "f"(v) : "memory");
}
__device__ __forceinline__ void csync() {
    asm volatile("barrier.cluster.arrive.aligned;" ::: "memory");
    asm volatile("barrier.cluster.wait.aligned;" ::: "memory");
}
__device__ __forceinline__ void ffma2(ull& acc, ull a, ull b) {
    asm("fma.rn.f32x2 %0, %1, %2, %0;" : "+l"(acc) : "l"(a), "l"(b));
}
__device__ __forceinline__ float2 u2f2(ull u) {
    float2 f;
    asm("mov.b64 {%0, %1}, %2;" : "=f"(f.x), "=f"(f.y) : "l"(u));
    return f;
}
__device__ __forceinline__ ull pk(float lo, float hi) {
    ull r;
    asm("mov.b64 %0, {%1, %2};" : "=l"(r) : "f"(lo), "f"(hi));
    return r;
}

__global__ void __launch_bounds__(NTHR, 1) __cluster_dims__(4, 1, 1)
lstm_cluster_kernel(
    const float* __restrict__ x,      // [128][1024]
    const float* __restrict__ w_ih1,  // [512][1]
    const float* __restrict__ w_hh1,  // [512][128]
    const float* __restrict__ b_ih1,
    const float* __restrict__ b_hh1,
    const float* __restrict__ w_ih2,  // [256][128]
    const float* __restrict__ w_hh2,  // [256][64]
    const float* __restrict__ b_ih2,
    const float* __restrict__ b_hh2,
    float* __restrict__ out)          // [128][64]
{
    __shared__ Smem sm;

    const int tid = threadIdx.x;
    const int q   = blockIdx.x & 3;   // cluster rank (dim slice)
    const int cid = blockIdx.x >> 2;  // batch group: batches 4*cid..4*cid+3

    // ---------------- thread roles ----------------
    // L1: row (g1, dl1) of this CTA's 32-dim slice; k-stripe ks1:
    //     thread owns k in { ks1*4 + 16*kk + e : kk=0..7, e=0..3 }
    const int ks1 = tid & 3;
    const int dl1 = (tid >> 2) & 31;
    const int g1  = tid >> 7;
    // L2: row (g2, dl2) of this CTA's 16-dim slice; k-stripe ks2:
    //     thread owns k in { ks2*4 + 32*kk + e : kk=0..5, e=0..3 }
    const int ks2 = tid & 7;
    const int dl2 = (tid >> 3) & 15;
    const int g2  = tid >> 7;

    // ---------------- one-time: weights -> registers (striped) ----------------
    const int row1w = g1 * 128 + 32 * q + dl1;
    ulonglong2 w1u[8];
    {
        const float* wr = w_hh1 + row1w * 128 + ks1 * 4;
#pragma unroll
        for (int kk = 0; kk < 8; kk++) {
            float4 f = *reinterpret_cast<const float4*>(wr + kk * 16);
            w1u[kk].x = pk(f.x, f.y);
            w1u[kk].y = pk(f.z, f.w);
        }
    }
    const int row2w = g2 * 64 + 16 * q + dl2;
    ulonglong2 w2u[6];
    {
#pragma unroll
        for (int kk = 0; kk < 6; kk++) {
            int k0 = ks2 * 4 + kk * 32;   // 4-aligned; chunk never straddles 128
            float f[4];
#pragma unroll
            for (int e = 0; e < 4; e++) {
                int k = k0 + e;
                f[e] = (k < 128) ? w_ih2[row2w * 128 + k] : w_hh2[row2w * 64 + (k - 128)];
            }
            w2u[kk].x = pk(f[0], f[1]);
            w2u[kk].y = pk(f[2], f[3]);
        }
    }

    // combiner constants
    float wihc[4], b1c[4];             // tid < 128 : L1 combiner for (b=tid&3, d=tid>>2)
    if (tid < 128) {
        int d = tid >> 2;
#pragma unroll
        for (int g = 0; g < 4; g++) {
            int row = g * 128 + 32 * q + d;
            wihc[g] = w_ih1[row];
            b1c[g]  = b_ih1[row] + b_hh1[row];
        }
    }
    float b2c[4];                      // tid < 64 : L2 combiner for (b=tid&3, d=tid>>2)
    if (tid < 64) {
        int d2 = 16 * q + (tid >> 2);
#pragma unroll
        for (int g = 0; g < 4; g++) b2c[g] = b_ih2[g * 64 + d2] + b_hh2[g * 64 + d2];
    }

    // ---------------- init smem: x staging + zero hc ----------------
    for (int idx = tid; idx < 4 * 1024; idx += NTHR) {
        int b = idx >> 10, t = idx & 1023;
        sm.xs[b][t] = x[(4 * cid + b) * 1024 + t];
    }
    for (int idx = tid; idx < 2 * 4 * 196; idx += NTHR)
        (&sm.hc[0][0][0])[idx] = 0.0f;

    csync();  // all cluster CTAs' smem ready

    float c1 = 0.0f, c2 = 0.0f;

    for (int i = 0; i <= Tlen; i++) {
        const int pc = i & 1, pp = pc ^ 1;

        // ---- L1 partials: all 4 batches, striped k-quarter, weights in regs ----
        if (i < Tlen) {
            float s[4];
#pragma unroll
            for (int b = 0; b < 4; b++) {
                const ulonglong2* hp =
                    reinterpret_cast<const ulonglong2*>(&sm.hc[pp][b][0]);
                ull a0 = 0ull, a1 = 0ull;
#pragma unroll
                for (int kk = 0; kk < 8; kk++) {
                    ulonglong2 h = hp[ks1 + 4 * kk];   // banks 4*ks1: conflict-free
                    ffma2(a0, h.x, w1u[kk].x);
                    ffma2(a1, h.y, w1u[kk].y);
                }
                float2 f0 = u2f2(a0), f1 = u2f2(a1);
                float v = (f0.x + f0.y) + (f1.x + f1.y);
                v += __shfl_xor_sync(0xffffffffu, v, 1);
                v += __shfl_xor_sync(0xffffffffu, v, 2);
                s[b] = v;
            }
            float v = (ks1 == 0) ? s[0] : (ks1 == 1) ? s[1] : (ks1 == 2) ? s[2] : s[3];
            sm.a1[g1 * 128 + dl1 * 4 + ks1] = v;
        }

        // ---- L2 partials: all 4 batches, striped k-eighth over [h1 ++ h2] ----
        if (i >= 1) {
            float s[4];
#pragma unroll
            for (int b = 0; b < 4; b++) {
                const ulonglong2* hp =
                    reinterpret_cast<const ulonglong2*>(&sm.hc[pp][b][0]);
                ull a0 = 0ull, a1 = 0ull;
#pragma unroll
                for (int kk = 0; kk < 6; kk++) {
                    ulonglong2 h = hp[ks2 + 8 * kk];   // banks 4*ks2: conflict-free
                    ffma2(a0, h.x, w2u[kk].x);
                    ffma2(a1, h.y, w2u[kk].y);
                }
                float2 f0 = u2f2(a0), f1 = u2f2(a1);
                float v = (f0.x + f0.y) + (f1.x + f1.y);
                v += __shfl_xor_sync(0xffffffffu, v, 1);
                v += __shfl_xor_sync(0xffffffffu, v, 2);
                v += __shfl_xor_sync(0xffffffffu, v, 4);
                s[b] = v;
            }
            if (ks2 < 4) {
                float v = (ks2 == 0) ? s[0] : (ks2 == 1) ? s[1] : (ks2 == 2) ? s[2] : s[3];
                sm.a2[g2 * 64 + dl2 * 4 + ks2] = v;
            }
        }

        __syncthreads();

        // ---- L1 combine + scatter h1 to all cluster CTAs ----
        if (i < Tlen && tid < 128) {
            int b = tid & 3, d = tid >> 2;
            float xv = sm.xs[b][i];
            float ai = fmaf(xv, wihc[0], sm.a1[tid]       + b1c[0]);
            float af = fmaf(xv, wihc[1], sm.a1[128 + tid] + b1c[1]);
            float ag = fmaf(xv, wihc[2], sm.a1[256 + tid] + b1c[2]);
            float ao = fmaf(xv, wihc[3], sm.a1[384 + tid] + b1c[3]);
            c1 = sigm(af) * c1 + sigm(ai) * tanhf(ag);
            float h = sigm(ao) * tanhf(c1);
            uint32_t dst = s2u(&sm.hc[pc][b][32 * q + d]);
            stc(dst, 0, h); stc(dst, 1, h); stc(dst, 2, h); stc(dst, 3, h);
        }

        // ---- L2 combine (one step behind) + scatter h2 / final output ----
        if (i >= 1 && tid < 64) {
            int b = tid & 3, d = tid >> 2;
            float ai = sm.a2[tid]       + b2c[0];
            float af = sm.a2[64 + tid]  + b2c[1];
            float ag = sm.a2[128 + tid] + b2c[2];
            float ao = sm.a2[192 + tid] + b2c[3];
            c2 = sigm(af) * c2 + sigm(ai) * tanhf(ag);
            float h = sigm(ao) * tanhf(c2);
            if (i == Tlen) {
                out[(4 * cid + b) * 64 + 16 * q + d] = h;
            } else {
                uint32_t dst = s2u(&sm.hc[pc][b][128 + 16 * q + d]);
                stc(dst, 0, h); stc(dst, 1, h); stc(dst, 2, h); stc(dst, 3, h);
            }
        }

        if (i < Tlen) csync();  // release our h writes / acquire peers'
    }
}

extern "C" void kernel_launch(void* const* d_in, const int* in_sizes, int n_in,
                              void* d_out, int out_size) {
    const float* x     = (const float*)d_in[0];
    const float* w_ih1 = (const float*)d_in[1];
    const float* w_hh1 = (const float*)d_in[2];
    const float* b_ih1 = (const float*)d_in[3];
    const float* b_hh1 = (const float*)d_in[4];
    const float* w_ih2 = (const float*)d_in[5];
    const float* w_hh2 = (const float*)d_in[6];
    const float* b_ih2 = (const float*)d_in[7];
    const float* b_hh2 = (const float*)d_in[8];
    float* out = (float*)d_out;

    lstm_cluster_kernel<<<NCTA, NTHR>>>(
        x, w_ih1, w_hh1, b_ih1, b_hh1, w_ih2, w_hh2, b_ih2, b_hh2, out);
    (void)in_sizes; (void)n_in; (void)out_size;
}